// round 8
// baseline (speedup 1.0000x reference)
#include <cuda_runtime.h>
#include <math.h>

// Fused LoRA-QKV + flash attention + output projection, fp32, packed-f32x2.
// B=2, N=2048, C=1024, H=16, hd=64, R=4. Four launches:
//   lora_a -> qkv GEMM (bias+LoRA epilogue, scatter to [B,H,N,hd])
//   -> flash attention -> proj GEMM.
// All FFMA-heavy loops use PTX fma.rn.f32x2 (B300 FFMA2; bitwise identical
// to scalar FMA pairs, 2 fp32 FMAs per issue slot).

// Problem constants
#define BB 2
#define NN 2048
#define CC 1024
#define HH 16
#define HD 64
#define RR 4
#define MM (BB*NN)        // 4096 rows
#define QKV_OUT (3*CC)    // 3072

// ---------------- packed f32x2 helpers (B300: FFMA2 via PTX only) -----------
#define FMA2(d, a, b, c) \
    asm("fma.rn.f32x2 %0, %1, %2, %3;" : "=l"(d) : "l"(a), "l"(b), "l"(c))
#define MUL2(d, a, b) \
    asm("mul.rn.f32x2 %0, %1, %2;" : "=l"(d) : "l"(a), "l"(b))

__device__ __forceinline__ unsigned long long pack2(float lo, float hi) {
    unsigned long long r;
    asm("mov.b64 %0, {%1, %2};" : "=l"(r) : "f"(lo), "f"(hi));
    return r;
}
__device__ __forceinline__ float2 unpack2(unsigned long long v) {
    float2 r;
    asm("mov.b64 {%0, %1}, %2;" : "=f"(r.x), "=f"(r.y) : "l"(v));
    return r;
}
struct ull2 { unsigned long long x, y; };

// ---------------- scratch (device globals; no allocations allowed) ----------
__device__ float g_a[MM * 8];                         // [M, 2R] lora intermediate
__device__ float g_qkv[3][BB * HH * NN * HD];         // q,k,v each [B,H,N,hd]
__device__ float g_attn[MM * CC];                     // attention out, [B*N, C]

// ---------------- kernel 1: a = x @ lora_A^T  ([M, 8]) ----------------------
__global__ __launch_bounds__(256) void lora_a_kernel(
    const float* __restrict__ x, const float* __restrict__ lora_A)
{
    __shared__ float xs[CC];
    int m = blockIdx.x;
    const float* xr = x + (size_t)m * CC;
    for (int i = threadIdx.x; i < CC; i += 256) xs[i] = xr[i];
    __syncthreads();

    int w = threadIdx.x >> 5;        // 8 warps -> 8 lora rows
    int lane = threadIdx.x & 31;
    const float* Ar = lora_A + w * CC;
    float s = 0.f;
    for (int i = lane; i < CC; i += 32) s += xs[i] * Ar[i];
    #pragma unroll
    for (int o = 16; o > 0; o >>= 1) s += __shfl_down_sync(0xffffffffu, s, o);
    if (lane == 0) g_a[m * 8 + w] = s;
}

// ---------------- kernel 2/4: tiled SGEMM  C = A @ W^T ----------------------
// 128x128x8 tile, 256 threads, 8x8 per thread, double-buffered smem with
// register prefetch. Inner product uses packed fma.rn.f32x2: accumulators
// paired along j; A is stored DUPLICATED in smem ((a,a) pairs) so broadcast
// pairs load directly via LDS.128 with no pack instructions.
template <int EPI>
__global__ __launch_bounds__(256) void gemm_kernel(
    const float* __restrict__ A_in, const float* __restrict__ W,
    const float* __restrict__ bias, const float* __restrict__ loraB,
    float* __restrict__ out)
{
    const float* A = (EPI == 0) ? A_in : (const float*)g_attn;

    // Asd: A duplicated ((v,v) per element): 256 floats/row + pad to 264.
    // Bs: 128 floats/row + pad to 132. Both rows stay 16B-aligned.
    __shared__ __align__(16) float Asd[2][8][264];
    __shared__ __align__(16) float Bs[2][8][132];

    const int m0 = blockIdx.y * 128;
    const int n0 = blockIdx.x * 128;
    const int tid = threadIdx.x;
    const int lrow = tid >> 1;            // 0..127
    const int lseg = (tid & 1) * 4;       // 0 or 4
    const int ty = tid >> 4;              // 0..15 (row group)
    const int tx = tid & 15;              // 0..15 (col group)

    unsigned long long acc2[8][4];        // (c[i][2j], c[i][2j+1]) pairs
    #pragma unroll
    for (int i = 0; i < 8; i++)
        #pragma unroll
        for (int j = 0; j < 4; j++) acc2[i][j] = 0ull;   // (0.f, 0.f)

    const size_t arow = (size_t)(m0 + lrow) * 1024;
    const size_t wrow = (size_t)(n0 + lrow) * 1024;

    // prologue: load tile 0 -> regs -> smem buf 0
    float4 av = *(const float4*)&A[arow + 0 + lseg];
    float4 wv = *(const float4*)&W[wrow + 0 + lseg];
    ((float2*)&Asd[0][lseg + 0][0])[lrow] = make_float2(av.x, av.x);
    ((float2*)&Asd[0][lseg + 1][0])[lrow] = make_float2(av.y, av.y);
    ((float2*)&Asd[0][lseg + 2][0])[lrow] = make_float2(av.z, av.z);
    ((float2*)&Asd[0][lseg + 3][0])[lrow] = make_float2(av.w, av.w);
    Bs[0][lseg + 0][lrow] = wv.x; Bs[0][lseg + 1][lrow] = wv.y;
    Bs[0][lseg + 2][lrow] = wv.z; Bs[0][lseg + 3][lrow] = wv.w;
    __syncthreads();

    const int NT = 1024 / 8;          // 128 K-steps
    for (int t = 0; t < NT; t++) {
        const int cur = t & 1;
        // prefetch next tile into registers (overlaps FMA block below)
        if (t + 1 < NT) {
            const int k0 = (t + 1) * 8;
            av = *(const float4*)&A[arow + k0 + lseg];
            wv = *(const float4*)&W[wrow + k0 + lseg];
        }

        #pragma unroll
        for (int kk = 0; kk < 8; kk++) {
            // a broadcast pairs: 4x LDS.128 = 8 pairs (a_i, a_i)
            const ull2* ap = (const ull2*)&Asd[cur][kk][ty * 16];
            const ull2* bp = (const ull2*)&Bs[cur][kk][tx * 8];
            ull2 a01 = ap[0], a23 = ap[1], a45 = ap[2], a67 = ap[3];
            ull2 b03 = bp[0], b47 = bp[1];
            unsigned long long af2[8] = { a01.x, a01.y, a23.x, a23.y,
                                          a45.x, a45.y, a67.x, a67.y };
            unsigned long long bf2[4] = { b03.x, b03.y, b47.x, b47.y };
            #pragma unroll
            for (int i = 0; i < 8; i++)
                #pragma unroll
                for (int j = 0; j < 4; j++)
                    FMA2(acc2[i][j], af2[i], bf2[j], acc2[i][j]);
        }

        if (t + 1 < NT) {
            const int nxt = cur ^ 1;
            ((float2*)&Asd[nxt][lseg + 0][0])[lrow] = make_float2(av.x, av.x);
            ((float2*)&Asd[nxt][lseg + 1][0])[lrow] = make_float2(av.y, av.y);
            ((float2*)&Asd[nxt][lseg + 2][0])[lrow] = make_float2(av.z, av.z);
            ((float2*)&Asd[nxt][lseg + 3][0])[lrow] = make_float2(av.w, av.w);
            Bs[nxt][lseg + 0][lrow] = wv.x; Bs[nxt][lseg + 1][lrow] = wv.y;
            Bs[nxt][lseg + 2][lrow] = wv.z; Bs[nxt][lseg + 3][lrow] = wv.w;
            __syncthreads();
        }
    }

    if (EPI == 0) {
        // bias + LoRA delta + scatter to q/k/v [B,H,N,hd]
        #pragma unroll
        for (int i = 0; i < 8; i++) {
            const int m = m0 + ty * 8 + i;
            const int b = m >> 11;          // /2048
            const int n = m & 2047;
            float accr[8];
            #pragma unroll
            for (int jp = 0; jp < 4; jp++) {
                float2 u = unpack2(acc2[i][jp]);
                accr[2 * jp] = u.x; accr[2 * jp + 1] = u.y;
            }
            const float a0 = g_a[m * 8 + 0], a1 = g_a[m * 8 + 1];
            const float a2 = g_a[m * 8 + 2], a3 = g_a[m * 8 + 3];
            const float a4 = g_a[m * 8 + 4], a5 = g_a[m * 8 + 5];
            const float a6 = g_a[m * 8 + 6], a7 = g_a[m * 8 + 7];
            #pragma unroll
            for (int j = 0; j < 8; j++) {
                const int o = n0 + tx * 8 + j;
                const int g = o >> 10;      // 0=q,1=k,2=v
                const int c = o & 1023;
                float v = accr[j] + bias[o];
                if (g == 0) {
                    const float* lb = &loraB[c * 4];
                    v += 0.25f * (a0 * lb[0] + a1 * lb[1] + a2 * lb[2] + a3 * lb[3]);
                } else if (g == 2) {
                    const float* lb = &loraB[(1024 + c) * 4];
                    v += 0.25f * (a4 * lb[0] + a5 * lb[1] + a6 * lb[2] + a7 * lb[3]);
                }
                const int h = c >> 6;
                const int d = c & 63;
                g_qkv[g][(((size_t)(b * HH + h)) * NN + n) * HD + d] = v;
            }
        }
    } else {
        #pragma unroll
        for (int i = 0; i < 8; i++) {
            const int m = m0 + ty * 8 + i;
            #pragma unroll
            for (int jp = 0; jp < 4; jp++) {
                float2 u = unpack2(acc2[i][jp]);
                const int o = n0 + tx * 8 + 2 * jp;
                out[(size_t)m * 1024 + o]     = u.x + bias[o];
                out[(size_t)m * 1024 + o + 1] = u.y + bias[o + 1];
            }
        }
    }
}

// ---------------- kernel 3: flash attention per (b,h) -----------------------
// grid = (32, 16). One query row per thread; q and acc live in registers as
// packed f32x2 pairs; K/V 32-key tiles in smem (broadcast reads). Softmax in
// the log2 domain (scale*log2e folded into q; bare exp2f). QK and PV products
// use fma.rn.f32x2 (2 fp32 FMA per issue, bitwise identical to scalar).
__global__ __launch_bounds__(128) void attn_kernel()
{
    const int bh = blockIdx.x;              // 0..31
    const int b  = bh >> 4;
    const int h  = bh & 15;
    const int row = blockIdx.y * 128 + threadIdx.x;
    const int t = threadIdx.x;

    __shared__ __align__(16) float4 Ks[32 * 16];
    __shared__ __align__(16) float4 Vs[32 * 16];

    const float qscale = 0.125f * 1.4426950408889634f;   // 64^-0.5 * log2(e)
    const float4* qp = (const float4*)&g_qkv[0][((size_t)bh * NN + row) * HD];
    unsigned long long q2[32];              // (q[2d], q[2d+1]) pairs, scaled
    #pragma unroll
    for (int i = 0; i < 16; i++) {
        float4 qv = qp[i];
        q2[2 * i]     = pack2(qv.x * qscale, qv.y * qscale);
        q2[2 * i + 1] = pack2(qv.z * qscale, qv.w * qscale);
    }

    unsigned long long acc2[32];            // packed output accumulator pairs
    #pragma unroll
    for (int i = 0; i < 32; i++) acc2[i] = 0ull;
    float mval = -1e30f, l = 0.f;           // running max & denom, log2 domain

    const float4* kbase = (const float4*)&g_qkv[1][(size_t)bh * NN * HD];
    const float4* vbase = (const float4*)&g_qkv[2][(size_t)bh * NN * HD];

    for (int kt = 0; kt < NN / 32; kt++) {
        #pragma unroll
        for (int i = 0; i < 4; i++) {
            Ks[t + 128 * i] = kbase[kt * 512 + t + 128 * i];
            Vs[t + 128 * i] = vbase[kt * 512 + t + 128 * i];
        }
        __syncthreads();

        float s[32];
        #pragma unroll
        for (int j = 0; j < 32; j++) {
            // two packed accumulator chains for ILP, pairwise horizontal add
            unsigned long long sa = 0ull, sb = 0ull;
            const ull2* kp = (const ull2*)&Ks[j * 16];
            #pragma unroll
            for (int dd = 0; dd < 16; dd++) {
                ull2 kv = kp[dd];
                FMA2(sa, q2[2 * dd],     kv.x, sa);
                FMA2(sb, q2[2 * dd + 1], kv.y, sb);
            }
            float2 ua = unpack2(sa), ub = unpack2(sb);
            const float h0 = ua.x + ua.y;
            const float h1 = ub.x + ub.y;
            s[j] = h0 + h1;
        }

        float tmax = s[0];
        #pragma unroll
        for (int j = 1; j < 32; j++) tmax = fmaxf(tmax, s[j]);
        const float mnew = fmaxf(mval, tmax);
        const float corr = exp2f(mval - mnew);
        l *= corr;
        const unsigned long long c2 = pack2(corr, corr);
        #pragma unroll
        for (int i = 0; i < 32; i++) MUL2(acc2[i], acc2[i], c2);

        #pragma unroll
        for (int j = 0; j < 32; j++) {
            const float p = exp2f(s[j] - mnew);
            l += p;
            const unsigned long long p2 = pack2(p, p);
            const ull2* vp = (const ull2*)&Vs[j * 16];
            #pragma unroll
            for (int dd = 0; dd < 16; dd++) {
                ull2 vv = vp[dd];
                FMA2(acc2[2 * dd],     p2, vv.x, acc2[2 * dd]);
                FMA2(acc2[2 * dd + 1], p2, vv.y, acc2[2 * dd + 1]);
            }
        }
        mval = mnew;
        __syncthreads();
    }

    const float inv = 1.f / l;
    float4* outp = (float4*)&g_attn[((size_t)b * NN + row) * CC + h * HD];
    #pragma unroll
    for (int dd = 0; dd < 16; dd++) {
        float2 u0 = unpack2(acc2[2 * dd]);
        float2 u1 = unpack2(acc2[2 * dd + 1]);
        float4 o;
        o.x = u0.x * inv; o.y = u0.y * inv;
        o.z = u1.x * inv; o.w = u1.y * inv;
        outp[dd] = o;
    }
}

// ---------------- launch ----------------------------------------------------
extern "C" void kernel_launch(void* const* d_in, const int* in_sizes, int n_in,
                              void* d_out, int out_size)
{
    const float* x      = (const float*)d_in[0];
    const float* W_qkv  = (const float*)d_in[1];
    const float* b_qkv  = (const float*)d_in[2];
    const float* lora_A = (const float*)d_in[3];
    const float* lora_B = (const float*)d_in[4];
    const float* W_proj = (const float*)d_in[5];
    const float* b_proj = (const float*)d_in[6];
    // d_in[7] = idx: selects among 4 identical adapters in the reference;
    // the math is identical for all values, so it does not enter the kernel.
    float* out = (float*)d_out;

    // 1) lora intermediate a = x @ lora_A^T
    lora_a_kernel<<<MM, 256>>>(x, lora_A);

    // 2) qkv = x @ W_qkv^T + b + lora delta, scattered to [B,H,N,hd]
    gemm_kernel<0><<<dim3(QKV_OUT / 128, MM / 128), 256>>>(
        x, W_qkv, b_qkv, lora_B, nullptr);

    // 3) attention
    attn_kernel<<<dim3(BB * HH, NN / 128), 128>>>();

    // 4) out = attn @ W_proj^T + b_proj
    gemm_kernel<1><<<dim3(CC / 128, MM / 128), 256>>>(
        nullptr, W_proj, b_proj, nullptr, out);
}

// round 12
// speedup vs baseline: 1.1169x; 1.1169x over previous
#include <cuda_runtime.h>
#include <math.h>

// Fused LoRA-QKV + flash attention + output projection, fp32, packed-f32x2.
// R9/R10/R11: GEMM smem de-duplication (dup pairs built in registers via
// mov.b64, not stored dup in smem), vectorized epilogues, 4-chain QK dot.
// R8 profile showed gemm<1> L1=76% / fma=39% (smem-bound) — shift to ALU.

// Problem constants
#define BB 2
#define NN 2048
#define CC 1024
#define HH 16
#define HD 64
#define RR 4
#define MM (BB*NN)        // 4096 rows
#define QKV_OUT (3*CC)    // 3072

// ---------------- packed f32x2 helpers (B300: FFMA2 via PTX only) -----------
#define FMA2(d, a, b, c) \
    asm("fma.rn.f32x2 %0, %1, %2, %3;" : "=l"(d) : "l"(a), "l"(b), "l"(c))
#define MUL2(d, a, b) \
    asm("mul.rn.f32x2 %0, %1, %2;" : "=l"(d) : "l"(a), "l"(b))

__device__ __forceinline__ unsigned long long pack2(float lo, float hi) {
    unsigned long long r;
    asm("mov.b64 %0, {%1, %2};" : "=l"(r) : "f"(lo), "f"(hi));
    return r;
}
__device__ __forceinline__ float2 unpack2(unsigned long long v) {
    float2 r;
    asm("mov.b64 {%0, %1}, %2;" : "=f"(r.x), "=f"(r.y) : "l"(v));
    return r;
}
struct ull2 { unsigned long long x, y; };

// ---------------- scratch (device globals; no allocations allowed) ----------
__device__ float g_a[MM * 8];                         // [M, 2R] lora intermediate
__device__ float g_qkv[3][BB * HH * NN * HD];         // q,k,v each [B,H,N,hd]
__device__ float g_attn[MM * CC];                     // attention out, [B*N, C]

// ---------------- kernel 1: a = x @ lora_A^T  ([M, 8]) ----------------------
__global__ __launch_bounds__(256) void lora_a_kernel(
    const float* __restrict__ x, const float* __restrict__ lora_A)
{
    __shared__ float xs[CC];
    int m = blockIdx.x;
    const float* xr = x + (size_t)m * CC;
    for (int i = threadIdx.x; i < CC; i += 256) xs[i] = xr[i];
    __syncthreads();

    int w = threadIdx.x >> 5;        // 8 warps -> 8 lora rows
    int lane = threadIdx.x & 31;
    const float* Ar = lora_A + w * CC;
    float s = 0.f;
    for (int i = lane; i < CC; i += 32) s += xs[i] * Ar[i];
    #pragma unroll
    for (int o = 16; o > 0; o >>= 1) s += __shfl_down_sync(0xffffffffu, s, o);
    if (lane == 0) g_a[m * 8 + w] = s;
}

// ---------------- kernel 2/4: tiled SGEMM  C = A @ W^T ----------------------
// 128x128x8 tile, 256 threads, 8x8 per thread, double-buffered smem with
// register prefetch. A and B stored UNduplicated (4 LDS.128 per kk); the
// (a,a) broadcast pairs for fma.rn.f32x2 are built in registers (mov.b64,
// ALU pipe) so the L1/smem pipe carries only the minimal traffic.
template <int EPI>
__global__ __launch_bounds__(256, 2) void gemm_kernel(
    const float* __restrict__ A_in, const float* __restrict__ W,
    const float* __restrict__ bias, const float* __restrict__ loraB,
    float* __restrict__ out)
{
    const float* A = (EPI == 0) ? A_in : (const float*)g_attn;

    __shared__ __align__(16) float As[2][8][132];   // 132-pad: 16B-aligned rows
    __shared__ __align__(16) float Bs[2][8][132];

    const int m0 = blockIdx.y * 128;
    const int n0 = blockIdx.x * 128;
    const int tid = threadIdx.x;
    const int lrow = tid >> 1;            // 0..127
    const int lseg = (tid & 1) * 4;       // 0 or 4
    const int ty = tid >> 4;              // 0..15 (row group)
    const int tx = tid & 15;              // 0..15 (col group)

    unsigned long long acc2[8][4];        // (c[i][2j], c[i][2j+1]) pairs
    #pragma unroll
    for (int i = 0; i < 8; i++)
        #pragma unroll
        for (int j = 0; j < 4; j++) acc2[i][j] = 0ull;

    const size_t arow = (size_t)(m0 + lrow) * 1024;
    const size_t wrow = (size_t)(n0 + lrow) * 1024;

    // prologue: load tile 0 -> regs -> smem buf 0
    float4 av = *(const float4*)&A[arow + 0 + lseg];
    float4 wv = *(const float4*)&W[wrow + 0 + lseg];
    As[0][lseg + 0][lrow] = av.x; As[0][lseg + 1][lrow] = av.y;
    As[0][lseg + 2][lrow] = av.z; As[0][lseg + 3][lrow] = av.w;
    Bs[0][lseg + 0][lrow] = wv.x; Bs[0][lseg + 1][lrow] = wv.y;
    Bs[0][lseg + 2][lrow] = wv.z; Bs[0][lseg + 3][lrow] = wv.w;
    __syncthreads();

    const int NT = 1024 / 8;          // 128 K-steps
    for (int t = 0; t < NT; t++) {
        const int cur = t & 1;
        // prefetch next tile into registers (overlaps FMA block below)
        if (t + 1 < NT) {
            const int k0 = (t + 1) * 8;
            av = *(const float4*)&A[arow + k0 + lseg];
            wv = *(const float4*)&W[wrow + k0 + lseg];
        }

        #pragma unroll
        for (int kk = 0; kk < 8; kk++) {
            const float4 af0 = *(const float4*)&As[cur][kk][ty * 8];
            const float4 af1 = *(const float4*)&As[cur][kk][ty * 8 + 4];
            const ull2* bp = (const ull2*)&Bs[cur][kk][tx * 8];
            const ull2 b03 = bp[0], b47 = bp[1];
            const unsigned long long bf2[4] = { b03.x, b03.y, b47.x, b47.y };
            const float af[8] = { af0.x, af0.y, af0.z, af0.w,
                                  af1.x, af1.y, af1.z, af1.w };
            #pragma unroll
            for (int i = 0; i < 8; i++) {
                const unsigned long long ai = pack2(af[i], af[i]);
                #pragma unroll
                for (int j = 0; j < 4; j++)
                    FMA2(acc2[i][j], ai, bf2[j], acc2[i][j]);
            }
        }

        if (t + 1 < NT) {
            const int nxt = cur ^ 1;
            As[nxt][lseg + 0][lrow] = av.x; As[nxt][lseg + 1][lrow] = av.y;
            As[nxt][lseg + 2][lrow] = av.z; As[nxt][lseg + 3][lrow] = av.w;
            Bs[nxt][lseg + 0][lrow] = wv.x; Bs[nxt][lseg + 1][lrow] = wv.y;
            Bs[nxt][lseg + 2][lrow] = wv.z; Bs[nxt][lseg + 3][lrow] = wv.w;
            __syncthreads();
        }
    }

    // Each thread's 8 output columns are contiguous (o = n0+tx*8 .. +7) and
    // stay inside one qkv group and one head: vectorized loads/stores.
    const int base_o = n0 + tx * 8;
    const float4 bias0 = *(const float4*)&bias[base_o];
    const float4 bias1 = *(const float4*)&bias[base_o + 4];

    if (EPI == 0) {
        const int g = base_o >> 10;       // 0=q,1=k,2=v (uniform per tile)
        const int c0 = base_o & 1023;
        const int h = c0 >> 6;
        const int d0 = c0 & 63;
        const float* lbbase = (g == 0) ? &loraB[c0 * 4]
                                       : &loraB[(1024 + c0) * 4];

        #pragma unroll
        for (int i = 0; i < 8; i++) {
            const int m = m0 + ty * 8 + i;
            const int b = m >> 11;        // /2048
            const int n = m & 2047;
            float v[8];
            #pragma unroll
            for (int jp = 0; jp < 4; jp++) {
                float2 u = unpack2(acc2[i][jp]);
                v[2 * jp] = u.x; v[2 * jp + 1] = u.y;
            }
            v[0] += bias0.x; v[1] += bias0.y; v[2] += bias0.z; v[3] += bias0.w;
            v[4] += bias1.x; v[5] += bias1.y; v[6] += bias1.z; v[7] += bias1.w;

            if (g != 1) {
                const float4 aq = *(const float4*)&g_a[m * 8 + (g == 0 ? 0 : 4)];
                #pragma unroll
                for (int j = 0; j < 8; j++) {
                    const float4 lb = *(const float4*)&lbbase[j * 4];
                    v[j] += 0.25f * (aq.x * lb.x + aq.y * lb.y +
                                     aq.z * lb.z + aq.w * lb.w);
                }
            }
            float* dst = &g_qkv[g][(((size_t)(b * HH + h)) * NN + n) * HD + d0];
            *(float4*)dst = make_float4(v[0], v[1], v[2], v[3]);
            *(float4*)(dst + 4) = make_float4(v[4], v[5], v[6], v[7]);
        }
    } else {
        #pragma unroll
        for (int i = 0; i < 8; i++) {
            const int m = m0 + ty * 8 + i;
            float v[8];
            #pragma unroll
            for (int jp = 0; jp < 4; jp++) {
                float2 u = unpack2(acc2[i][jp]);
                v[2 * jp] = u.x; v[2 * jp + 1] = u.y;
            }
            v[0] += bias0.x; v[1] += bias0.y; v[2] += bias0.z; v[3] += bias0.w;
            v[4] += bias1.x; v[5] += bias1.y; v[6] += bias1.z; v[7] += bias1.w;
            float* dst = &out[(size_t)m * 1024 + base_o];
            *(float4*)dst = make_float4(v[0], v[1], v[2], v[3]);
            *(float4*)(dst + 4) = make_float4(v[4], v[5], v[6], v[7]);
        }
    }
}

// ---------------- kernel 3: flash attention per (b,h) -----------------------
// grid = (32, 16). One query row per thread; q and acc live in registers as
// packed f32x2 pairs; K/V 32-key tiles in smem (broadcast reads). Softmax in
// the log2 domain (scale*log2e folded into q; bare exp2f). QK uses 4 packed
// accumulator chains for dep-latency slack; PV has natural ILP across acc2.
__global__ __launch_bounds__(128) void attn_kernel()
{
    const int bh = blockIdx.x;              // 0..31
    const int b  = bh >> 4;
    const int h  = bh & 15;
    const int row = blockIdx.y * 128 + threadIdx.x;
    const int t = threadIdx.x;

    __shared__ __align__(16) float4 Ks[32 * 16];
    __shared__ __align__(16) float4 Vs[32 * 16];

    const float qscale = 0.125f * 1.4426950408889634f;   // 64^-0.5 * log2(e)
    const float4* qp = (const float4*)&g_qkv[0][((size_t)bh * NN + row) * HD];
    unsigned long long q2[32];              // (q[2d], q[2d+1]) pairs, scaled
    #pragma unroll
    for (int i = 0; i < 16; i++) {
        float4 qv = qp[i];
        q2[2 * i]     = pack2(qv.x * qscale, qv.y * qscale);
        q2[2 * i + 1] = pack2(qv.z * qscale, qv.w * qscale);
    }

    unsigned long long acc2[32];            // packed output accumulator pairs
    #pragma unroll
    for (int i = 0; i < 32; i++) acc2[i] = 0ull;
    float mval = -1e30f, l = 0.f;           // running max & denom, log2 domain

    const float4* kbase = (const float4*)&g_qkv[1][(size_t)bh * NN * HD];
    const float4* vbase = (const float4*)&g_qkv[2][(size_t)bh * NN * HD];

    for (int kt = 0; kt < NN / 32; kt++) {
        #pragma unroll
        for (int i = 0; i < 4; i++) {
            Ks[t + 128 * i] = kbase[kt * 512 + t + 128 * i];
            Vs[t + 128 * i] = vbase[kt * 512 + t + 128 * i];
        }
        __syncthreads();

        float s[32];
        #pragma unroll
        for (int j = 0; j < 32; j++) {
            // four packed accumulator chains, pairwise horizontal add
            unsigned long long s0 = 0ull, s1 = 0ull, s2 = 0ull, s3 = 0ull;
            const ull2* kp = (const ull2*)&Ks[j * 16];
            #pragma unroll
            for (int dd = 0; dd < 16; dd += 2) {
                ull2 kva = kp[dd];
                ull2 kvb = kp[dd + 1];
                FMA2(s0, q2[2 * dd],     kva.x, s0);
                FMA2(s1, q2[2 * dd + 1], kva.y, s1);
                FMA2(s2, q2[2 * dd + 2], kvb.x, s2);
                FMA2(s3, q2[2 * dd + 3], kvb.y, s3);
            }
            float2 u0 = unpack2(s0), u1 = unpack2(s1);
            float2 u2 = unpack2(s2), u3 = unpack2(s3);
            s[j] = ((u0.x + u0.y) + (u1.x + u1.y)) +
                   ((u2.x + u2.y) + (u3.x + u3.y));
        }

        float tmax = s[0];
        #pragma unroll
        for (int j = 1; j < 32; j++) tmax = fmaxf(tmax, s[j]);
        const float mnew = fmaxf(mval, tmax);
        const float corr = exp2f(mval - mnew);
        l *= corr;
        const unsigned long long c2 = pack2(corr, corr);
        #pragma unroll
        for (int i = 0; i < 32; i++) MUL2(acc2[i], acc2[i], c2);

        #pragma unroll
        for (int j = 0; j < 32; j++) {
            const float p = exp2f(s[j] - mnew);
            l += p;
            const unsigned long long p2 = pack2(p, p);
            const ull2* vp = (const ull2*)&Vs[j * 16];
            #pragma unroll
            for (int dd = 0; dd < 16; dd++) {
                ull2 vv = vp[dd];
                FMA2(acc2[2 * dd],     p2, vv.x, acc2[2 * dd]);
                FMA2(acc2[2 * dd + 1], p2, vv.y, acc2[2 * dd + 1]);
            }
        }
        mval = mnew;
        __syncthreads();
    }

    const float inv = 1.f / l;
    float4* outp = (float4*)&g_attn[((size_t)b * NN + row) * CC + h * HD];
    #pragma unroll
    for (int dd = 0; dd < 16; dd++) {
        float2 u0 = unpack2(acc2[2 * dd]);
        float2 u1 = unpack2(acc2[2 * dd + 1]);
        float4 o;
        o.x = u0.x * inv; o.y = u0.y * inv;
        o.z = u1.x * inv; o.w = u1.y * inv;
        outp[dd] = o;
    }
}

// ---------------- launch ----------------------------------------------------
extern "C" void kernel_launch(void* const* d_in, const int* in_sizes, int n_in,
                              void* d_out, int out_size)
{
    const float* x      = (const float*)d_in[0];
    const float* W_qkv  = (const float*)d_in[1];
    const float* b_qkv  = (const float*)d_in[2];
    const float* lora_A = (const float*)d_in[3];
    const float* lora_B = (const float*)d_in[4];
    const float* W_proj = (const float*)d_in[5];
    const float* b_proj = (const float*)d_in[6];
    // d_in[7] = idx: selects among 4 identical adapters in the reference;
    // the math is identical for all values, so it does not enter the kernel.
    float* out = (float*)d_out;

    // 1) lora intermediate a = x @ lora_A^T
    lora_a_kernel<<<MM, 256>>>(x, lora_A);

    // 2) qkv = x @ W_qkv^T + b + lora delta, scattered to [B,H,N,hd]
    gemm_kernel<0><<<dim3(QKV_OUT / 128, MM / 128), 256>>>(
        x, W_qkv, b_qkv, lora_B, nullptr);

    // 3) attention
    attn_kernel<<<dim3(BB * HH, NN / 128), 128>>>();

    // 4) out = attn @ W_proj^T + b_proj
    gemm_kernel<1><<<dim3(CC / 128, MM / 128), 256>>>(
        nullptr, W_proj, b_proj, nullptr, out);
}